// round 10
// baseline (speedup 1.0000x reference)
#include <cuda_runtime.h>

// Problem constants
#define BATCH 1024
#define CCH   3
#define HH    224
#define WW    220
#define PROWS 4
#define PCOLS 5
#define NPATCH 20
#define HID   32
#define PH    56          // HH / PROWS
#define PW    44          // WW / PCOLS
#define V4_PER_ROW   55   // WW / 4 (full stripe row)
#define V4_PER_STRIPE (PH * V4_PER_ROW)   // 3080 float4 per (c, pr) stripe
#define MAIN_ITERS   12                   // 256*12 = 3072
#define TAIL_V4      8                    // 3080 - 3072 (all land in pc=4)
#define MEAN_DIV (CCH * PH * PW)          // 7392

// Scratch for contribs if the output buffer doesn't hold them
__device__ float g_contribs[BATCH * NPATCH];

// Kernel 1: CTA = (b, pr). Sweeps 3 contiguous 49,280 B channel-stripes with a
// 12-deep unrolled LDG.128 batch each, accumulating 5 patch-column sums across
// all channels. tid<5 then runs the complete per-patch MLP in-CTA (free,
// hidden under the memory stream) and writes contribs directly.
__global__ __launch_bounds__(256) void stripe_mlp_kernel(
    const float* __restrict__ x,
    const float* __restrict__ w1,
    const float* __restrict__ b1,
    const float* __restrict__ w2,
    const float* __restrict__ b2,
    float* __restrict__ contribs)
{
    const int blk = blockIdx.x;              // b*4 + pr
    const int pr  = blk & 3;
    const int b   = blk >> 2;
    const int tid = threadIdx.x;

    float a0 = 0.f, a1 = 0.f, a2 = 0.f, a3 = 0.f, a4 = 0.f;

    for (int c = 0; c < CCH; c++) {
        const float4* region = reinterpret_cast<const float4*>(
            x + ((size_t)(b * CCH + c) * HH + (size_t)pr * PH) * WW);

        // Batch all 12 loads up front: independent addresses, deep MLP.
        float4 d[MAIN_ITERS];
        #pragma unroll
        for (int u = 0; u < MAIN_ITERS; u++)
            d[u] = region[tid + u * 256];

        #pragma unroll
        for (int u = 0; u < MAIN_ITERS; u++) {
            float s = (d[u].x + d[u].y) + (d[u].z + d[u].w);
            int i  = tid + u * 256;
            int k  = i % V4_PER_ROW;     // float4 index within row [0,55)
            int pc = k / 11;             // patch column [0,5)
            if      (pc == 0) a0 += s;
            else if (pc == 1) a1 += s;
            else if (pc == 2) a2 += s;
            else if (pc == 3) a3 += s;
            else              a4 += s;
        }

        // Tail: i in [3072,3080) -> k in [47,54] -> all patch column 4.
        if (tid < TAIL_V4) {
            float4 t = region[MAIN_ITERS * 256 + tid];
            a4 += (t.x + t.y) + (t.z + t.w);
        }
    }

    // Block-reduce the 5 accumulators
    float accs[5] = {a0, a1, a2, a3, a4};
    __shared__ float red[5][8];
    const int lane = tid & 31;
    const int wrp  = tid >> 5;
    #pragma unroll
    for (int pc = 0; pc < 5; pc++) {
        float v = accs[pc];
        #pragma unroll
        for (int o = 16; o > 0; o >>= 1)
            v += __shfl_down_sync(0xffffffffu, v, o);
        if (lane == 0) red[pc][wrp] = v;
    }
    __syncthreads();

    if (tid < 5) {
        float s = 0.f;
        #pragma unroll
        for (int w = 0; w < 8; w++) s += red[tid][w];
        const float f = s * (1.0f / (float)MEAN_DIV);   // patch mean

        const int p = pr * PCOLS + tid;                 // patch index
        float acc = b2[p];
        const float* w1p = w1 + p * HID;
        const float* b1p = b1 + p * HID;
        const float* w2p = w2 + p * HID;
        #pragma unroll
        for (int k = 0; k < HID; k++) {
            float h = fmaf(f, w1p[k], b1p[k]);
            h = fmaxf(h, 0.0f);
            acc = fmaf(h, w2p[k], acc);
        }
        contribs[b * NPATCH + p] = acc;
    }
}

// Kernel 2: score only. One thread per batch item; contribs row = 80 B = 5
// aligned float4 loads from L2-hot memory.
__global__ __launch_bounds__(128) void score_kernel(
    const float* __restrict__ contribs,
    float* __restrict__ score)
{
    const int b = blockIdx.x * 128 + threadIdx.x;
    const float4* row = reinterpret_cast<const float4*>(contribs + b * NPATCH);
    float4 v0 = row[0], v1 = row[1], v2 = row[2], v3 = row[3], v4 = row[4];
    float s = ((v0.x + v0.y) + (v0.z + v0.w))
            + ((v1.x + v1.y) + (v1.z + v1.w))
            + ((v2.x + v2.y) + (v2.z + v2.w))
            + ((v3.x + v3.y) + (v3.z + v3.w))
            + ((v4.x + v4.y) + (v4.z + v4.w));
    score[b] = s;
}

extern "C" void kernel_launch(void* const* d_in, const int* in_sizes, int n_in,
                              void* d_out, int out_size)
{
    const float* x  = (const float*)d_in[0];
    const float* w1 = (const float*)d_in[1];
    const float* b1 = (const float*)d_in[2];
    const float* w2 = (const float*)d_in[3];
    const float* b2 = (const float*)d_in[4];

    float* out = (float*)d_out;
    float* score_ptr    = nullptr;
    float* contribs_ptr = nullptr;

    if (out_size == BATCH * (NPATCH + 1)) {
        score_ptr    = out;           // (score, contribs) concatenated
        contribs_ptr = out + BATCH;
    } else if (out_size == BATCH) {
        score_ptr = out;
        cudaGetSymbolAddress((void**)&contribs_ptr, g_contribs);
    } else if (out_size == BATCH * NPATCH) {
        contribs_ptr = out;
    } else {
        score_ptr    = out;
        contribs_ptr = out + BATCH;
    }

    stripe_mlp_kernel<<<BATCH * PROWS, 256>>>(x, w1, b1, w2, b2, contribs_ptr);
    if (score_ptr != nullptr) {
        score_kernel<<<BATCH / 128, 128>>>(contribs_ptr, score_ptr);
    }
}

// round 15
// speedup vs baseline: 1.0768x; 1.0768x over previous
#include <cuda_runtime.h>

// Problem constants
#define BATCH 1024
#define CCH   3
#define HH    224
#define WW    220
#define PROWS 4
#define PCOLS 5
#define NPATCH 20
#define HID   32
#define PH    56          // HH / PROWS
#define PW    44          // WW / PCOLS
#define V4_PER_ROW   55   // WW / 4 (full stripe row)
#define V4_PER_STRIPE (PH * V4_PER_ROW)   // 3080 float4 per (b,c,pr) stripe
#define MAIN_ITERS   12                   // 256*12 = 3072
#define TAIL_V4      8                    // 3080 - 3072 (all land in pc=4)
#define MEAN_DIV (CCH * PH * PW)          // 7392
#define CTAS_PER_B (CCH * PROWS)          // 12

// Per-(b, p, c) partial patch sums + arrival counters (replay-safe: last CTA resets).
__device__ float g_part[BATCH * NPATCH * CCH];
__device__ int   g_count[BATCH];
// Scratch for contribs if the output buffer doesn't hold them
__device__ float g_contribs[BATCH * NPATCH];

// One kernel: R7's proven memory engine (CTA = (b,c,pr), single 12-deep
// LDG.128 batch) + fence-counter epilogue: the last-arriving CTA of each b
// runs the 20 per-patch MLPs, writes contribs, and reduces the score.
__global__ __launch_bounds__(256) void stripe_fused_kernel(
    const float* __restrict__ x,
    const float* __restrict__ w1,
    const float* __restrict__ b1,
    const float* __restrict__ w2,
    const float* __restrict__ b2,
    float* __restrict__ contribs,
    float* __restrict__ score)
{
    const int blk = blockIdx.x;              // ((b*3 + c)*4 + pr), pr fastest
    const int pr  = blk & 3;
    const int bc  = blk >> 2;                // b*3 + c
    const int c   = bc % 3;
    const int b   = bc / 3;
    const int tid = threadIdx.x;

    const float4* region = reinterpret_cast<const float4*>(
        x + ((size_t)bc * HH + (size_t)pr * PH) * WW);

    // Batch all 12 loads up front: independent addresses, deep MLP_p.
    float4 d[MAIN_ITERS];
    #pragma unroll
    for (int u = 0; u < MAIN_ITERS; u++)
        d[u] = region[tid + u * 256];

    float a0 = 0.f, a1 = 0.f, a2 = 0.f, a3 = 0.f, a4 = 0.f;
    #pragma unroll
    for (int u = 0; u < MAIN_ITERS; u++) {
        float s = (d[u].x + d[u].y) + (d[u].z + d[u].w);
        int i  = tid + u * 256;
        int k  = i % V4_PER_ROW;     // float4 index within row [0,55)
        int pc = k / 11;             // patch column [0,5)
        if      (pc == 0) a0 += s;
        else if (pc == 1) a1 += s;
        else if (pc == 2) a2 += s;
        else if (pc == 3) a3 += s;
        else              a4 += s;
    }

    // Tail: i in [3072,3080) -> k in [47,54] -> all patch column 4.
    if (tid < TAIL_V4) {
        float4 t = region[MAIN_ITERS * 256 + tid];
        a4 += (t.x + t.y) + (t.z + t.w);
    }

    // Block-reduce the 5 accumulators
    float accs[5] = {a0, a1, a2, a3, a4};
    __shared__ float red[5][8];
    const int lane = tid & 31;
    const int wrp  = tid >> 5;
    #pragma unroll
    for (int pc = 0; pc < 5; pc++) {
        float v = accs[pc];
        #pragma unroll
        for (int o = 16; o > 0; o >>= 1)
            v += __shfl_down_sync(0xffffffffu, v, o);
        if (lane == 0) red[pc][wrp] = v;
    }
    __syncthreads();

    if (tid < 5) {
        float s = 0.f;
        #pragma unroll
        for (int w = 0; w < 8; w++) s += red[tid][w];
        // layout: (b*20 + p)*3 + c with p = pr*5 + pc
        g_part[((size_t)(b * PROWS + pr) * PCOLS + tid) * CCH + c] = s;
    }
    __syncthreads();

    // Arrival protocol (threadFenceReduction pattern)
    __shared__ int is_last;
    if (tid == 0) {
        __threadfence();                         // partials visible before count
        int old = atomicAdd(&g_count[b], 1);
        is_last = (old == CTAS_PER_B - 1);
    }
    __syncthreads();

    if (!is_last) return;

    // Last CTA for this b: finish everything. Warp 0 only.
    if (tid < 32) {
        __threadfence();                         // order reads after arrivals
        float contrib = 0.f;
        if (tid < NPATCH) {
            const float* gp = g_part + (size_t)(b * NPATCH + tid) * CCH;
            float f = ((gp[0] + gp[1]) + gp[2]) * (1.0f / (float)MEAN_DIV);

            float acc = b2[tid];
            const float* w1p = w1 + tid * HID;
            const float* b1p = b1 + tid * HID;
            const float* w2p = w2 + tid * HID;
            #pragma unroll
            for (int k = 0; k < HID; k++) {
                float h = fmaf(f, w1p[k], b1p[k]);
                h = fmaxf(h, 0.0f);
                acc = fmaf(h, w2p[k], acc);
            }
            contrib = acc;
            if (contribs != nullptr)
                contribs[b * NPATCH + tid] = acc;
        }
        // warp reduce 20 contribs (lanes >= 20 carry 0)
        float s = contrib;
        #pragma unroll
        for (int o = 16; o > 0; o >>= 1)
            s += __shfl_down_sync(0xffffffffu, s, o);
        if (tid == 0) {
            if (score != nullptr) score[b] = s;
            g_count[b] = 0;                      // reset for next graph replay
        }
    }
}

extern "C" void kernel_launch(void* const* d_in, const int* in_sizes, int n_in,
                              void* d_out, int out_size)
{
    const float* x  = (const float*)d_in[0];
    const float* w1 = (const float*)d_in[1];
    const float* b1 = (const float*)d_in[2];
    const float* w2 = (const float*)d_in[3];
    const float* b2 = (const float*)d_in[4];

    float* out = (float*)d_out;
    float* score_ptr    = nullptr;
    float* contribs_ptr = nullptr;

    if (out_size == BATCH * (NPATCH + 1)) {
        score_ptr    = out;           // (score, contribs) concatenated
        contribs_ptr = out + BATCH;
    } else if (out_size == BATCH) {
        score_ptr = out;
        cudaGetSymbolAddress((void**)&contribs_ptr, g_contribs);
    } else if (out_size == BATCH * NPATCH) {
        contribs_ptr = out;
    } else {
        score_ptr    = out;
        contribs_ptr = out + BATCH;
    }

    stripe_fused_kernel<<<BATCH * CCH * PROWS, 256>>>(
        x, w1, b1, w2, b2, contribs_ptr, score_ptr);
}